// round 13
// baseline (speedup 1.0000x reference)
#include <cuda_runtime.h>
#include <cuda_bf16.h>
#include <cstdint>
#include <math.h>

// ---------------- problem constants ----------------
#define B_   16
#define S_   2048
#define DIN  512
#define DH   1024
#define DH2  512
#define DOUT 10
#define M_   (B_ * S_)   // 32768

typedef __nv_bfloat16 bf16;

// ---------------- scratch (device globals; allocation-free) ----------------
__device__ bf16  g_inb [(size_t)M_ * DIN];
__device__ bf16  g_w1t [(size_t)(2 * DIN) * DIN];   // [N,K] bf16
__device__ bf16  g_w2t [(size_t)DH * (2 * DIN)];
__device__ bf16  g_w3t [(size_t)DH2 * DH];
__device__ bf16  g_h1b [(size_t)M_ * (2 * DIN)];
__device__ bf16  g_hb  [(size_t)M_ * DH];
__device__ float g_attn[(size_t)B_ * S_ * S_];      // fp32 scores
__device__ bf16  g_attnb[(size_t)B_ * S_ * S_];     // bf16 attn weights
__device__ bf16  g_ctxb[(size_t)M_ * DH];
__device__ float g_o   [(size_t)M_ * DH2];

// ---------------- helpers ----------------
__device__ __forceinline__ uint32_t smem_u32(const void* p) {
    uint32_t a;
    asm("{ .reg .u64 t; cvta.to.shared.u64 t, %1; cvt.u32.u64 %0, t; }" : "=r"(a) : "l"(p));
    return a;
}
__device__ __forceinline__ void cp16(uint32_t dst, const void* src) {
    asm volatile("cp.async.cg.shared.global [%0], [%1], 16;" :: "r"(dst), "l"(src));
}
#define CP_COMMIT() asm volatile("cp.async.commit_group;" ::: "memory")
#define CP_WAIT(N)  asm volatile("cp.async.wait_group %0;" :: "n"(N) : "memory")

__device__ __forceinline__ void ldsm_x4(uint32_t* r, uint32_t addr) {
    asm volatile("ldmatrix.sync.aligned.m8n8.x4.shared.b16 {%0,%1,%2,%3}, [%4];"
        : "=r"(r[0]), "=r"(r[1]), "=r"(r[2]), "=r"(r[3]) : "r"(addr));
}
__device__ __forceinline__ void ldsm_x4_t(uint32_t* r, uint32_t addr) {
    asm volatile("ldmatrix.sync.aligned.m8n8.x4.trans.shared.b16 {%0,%1,%2,%3}, [%4];"
        : "=r"(r[0]), "=r"(r[1]), "=r"(r[2]), "=r"(r[3]) : "r"(addr));
}
__device__ __forceinline__ void mma_bf16(float* d, const uint32_t* a, const uint32_t* b) {
    asm volatile(
        "mma.sync.aligned.m16n8k16.row.col.f32.bf16.bf16.f32 "
        "{%0,%1,%2,%3}, {%4,%5,%6,%7}, {%8,%9}, {%0,%1,%2,%3};"
        : "+f"(d[0]), "+f"(d[1]), "+f"(d[2]), "+f"(d[3])
        : "r"(a[0]), "r"(a[1]), "r"(a[2]), "r"(a[3]), "r"(b[0]), "r"(b[1]));
}

// ---------------- GEMM geometry ----------------
// CTA 128x128, BK=32 bf16, 4-stage cp.async ring (1 sync/stage),
// 8 warps = 2(m) x 4(n), warp tile 64x32, m16n8k16.
#define PA 80
#define PBN 272
#define ABYTES (128 * PA)          // 10240
#define STAGES 4

// TRI: 1D triangular tile grid (scores): blockIdx.x -> (bi>=bj), z = batch,
//      plus per-sub-tile MMA skip on diagonal tiles.
template<typename TO, bool RELU, bool HAS_BIAS, bool BNN, bool TRI, bool KCUT, bool REVY>
__global__ void __launch_bounds__(256, 2)
gemm_bf(const bf16* __restrict__ A, const bf16* __restrict__ Bsrc,
        const float* __restrict__ bias, TO* __restrict__ C,
        int lda, int ldb, int ldc, int K,
        size_t strA, size_t strB, size_t strC)
{
    constexpr int BBYTES = BNN ? (32 * PBN) : ABYTES;
    constexpr int SB     = ABYTES + BBYTES;

    int m0, n0;
    if (TRI) {
        // decode x -> (bi, bj), bi >= bj, bi in [0,16)
        const int x = blockIdx.x;
        int bi = (int)((sqrtf(8.0f * (float)x + 1.0f) - 1.0f) * 0.5f);
        while ((bi + 1) * (bi + 2) / 2 <= x) bi++;
        while (bi * (bi + 1) / 2 > x) bi--;
        const int bj = x - bi * (bi + 1) / 2;
        m0 = bi * 128;
        n0 = bj * 128;
    } else {
        const int by = REVY ? (gridDim.y - 1 - blockIdx.y) : blockIdx.y;
        m0 = by * 128;
        n0 = blockIdx.x * 128;
    }

    A    += (size_t)blockIdx.z * strA;
    Bsrc += (size_t)blockIdx.z * strB;
    C    += (size_t)blockIdx.z * strC;

    const int Keff = KCUT ? ((m0 + 128) < K ? (m0 + 128) : K) : K;
    const int NC = Keff >> 5;

    extern __shared__ char smem[];
    const uint32_t sb = smem_u32(smem);

    const int tid  = threadIdx.x;
    const int lane = tid & 31;
    const int wid  = tid >> 5;
    const int wm   = wid & 1;
    const int wn   = wid >> 1;
    const int fc   = lane & 3;
    const int fr   = lane >> 2;

    const int f_row = tid >> 1, f_hf = tid & 1;
    const int bn_r  = tid >> 4, bn_c = tid & 15;

    // Liveness masks only for the triangular (scores) instantiation.
    // Sub-MMA covers rows [m0+wm*64+mt*16, +15], cols [n0+wn*32+nt*8, +7];
    // dead iff entirely above the diagonal (softmax masks those by index).
    bool live[4][4];
    if constexpr (TRI) {
        #pragma unroll
        for (int mt = 0; mt < 4; ++mt)
            #pragma unroll
            for (int nt = 0; nt < 4; ++nt)
                live[mt][nt] =
                    (n0 + wn * 32 + nt * 8) <= (m0 + wm * 64 + mt * 16 + 15);
    }

    #define FILL(stage, c) do {                                                    \
        const uint32_t _ab = sb + (stage) * SB;                                     \
        const uint32_t _bb = _ab + ABYTES;                                          \
        const int _k = (c) << 5;                                                    \
        _Pragma("unroll")                                                           \
        for (int j = 0; j < 2; j++) {                                               \
            const int ch = f_hf * 2 + j;                                            \
            cp16(_ab + (uint32_t)(f_row * PA + ch * 16),                            \
                 A + (size_t)(m0 + f_row) * lda + _k + ch * 8);                     \
        }                                                                           \
        if (BNN) {                                                                  \
            cp16(_bb + (uint32_t)(bn_r * PBN + bn_c * 16),                          \
                 Bsrc + (size_t)(_k + bn_r) * ldb + n0 + bn_c * 8);                 \
            cp16(_bb + (uint32_t)((bn_r + 16) * PBN + bn_c * 16),                   \
                 Bsrc + (size_t)(_k + bn_r + 16) * ldb + n0 + bn_c * 8);            \
        } else {                                                                    \
            _Pragma("unroll")                                                       \
            for (int j = 0; j < 2; j++) {                                           \
                const int ch = f_hf * 2 + j;                                        \
                cp16(_bb + (uint32_t)(f_row * PA + ch * 16),                        \
                     Bsrc + (size_t)(n0 + f_row) * ldb + _k + ch * 8);              \
            }                                                                       \
        }                                                                           \
    } while (0)

    float acc[4][4][4];
    #pragma unroll
    for (int i = 0; i < 4; i++)
        #pragma unroll
        for (int j = 0; j < 4; j++)
            #pragma unroll
            for (int r = 0; r < 4; r++) acc[i][j][r] = 0.0f;

    #pragma unroll
    for (int s = 0; s < STAGES - 1; s++) {
        if (s < NC) FILL(s, s);
        CP_COMMIT();
    }

    const uint32_t aoff   = (uint32_t)((lane & 15) * PA + (lane >> 4) * 16);
    const uint32_t boffNT = (uint32_t)((((lane >> 4) & 1) * 8 + (lane & 7)) * PA
                                       + ((lane >> 3) & 1) * 16);
    const uint32_t boffNN = (uint32_t)((lane & 15) * PBN + (lane >> 4) * 16);

    for (int c = 0; c < NC; ++c) {
        CP_WAIT(STAGES - 2);
        __syncthreads();
        if (c + STAGES - 1 < NC) FILL((c + STAGES - 1) & 3, c + STAGES - 1);
        CP_COMMIT();

        const uint32_t stb   = sb + (c & 3) * SB;
        const uint32_t aBase = stb + (uint32_t)(wm * 64) * PA + aoff;
        const uint32_t bBase = BNN
            ? (stb + ABYTES + (uint32_t)(wn * 32) * 2 + boffNN)
            : (stb + ABYTES + (uint32_t)(wn * 32) * PA + boffNT);

        #pragma unroll
        for (int s = 0; s < 2; ++s) {
            uint32_t bf[4][2];
            if (BNN) {
                uint32_t t[4];
                ldsm_x4_t(t, bBase + (uint32_t)(s * 16) * PBN);
                bf[0][0] = t[0]; bf[0][1] = t[1]; bf[1][0] = t[2]; bf[1][1] = t[3];
                ldsm_x4_t(t, bBase + (uint32_t)(s * 16) * PBN + 32);
                bf[2][0] = t[0]; bf[2][1] = t[1]; bf[3][0] = t[2]; bf[3][1] = t[3];
            } else {
                uint32_t t[4];
                ldsm_x4(t, bBase + s * 32);
                bf[0][0] = t[0]; bf[0][1] = t[1]; bf[1][0] = t[2]; bf[1][1] = t[3];
                ldsm_x4(t, bBase + 16 * PA + s * 32);
                bf[2][0] = t[0]; bf[2][1] = t[1]; bf[3][0] = t[2]; bf[3][1] = t[3];
            }
            #pragma unroll
            for (int mt = 0; mt < 4; ++mt) {
                uint32_t af[4];
                ldsm_x4(af, aBase + (uint32_t)(mt * 16) * PA + s * 32);
                #pragma unroll
                for (int nt = 0; nt < 4; ++nt) {
                    if constexpr (TRI) {
                        if (live[mt][nt])
                            mma_bf16(acc[mt][nt], af, bf[nt]);
                    } else {
                        mma_bf16(acc[mt][nt], af, bf[nt]);
                    }
                }
            }
        }
    }

    #pragma unroll
    for (int mt = 0; mt < 4; ++mt) {
        #pragma unroll
        for (int nt = 0; nt < 4; ++nt) {
            const int row = m0 + wm * 64 + mt * 16 + fr;
            const int col = n0 + wn * 32 + nt * 8 + 2 * fc;
            float b0 = 0.f, b1 = 0.f;
            if (HAS_BIAS) { b0 = bias[col]; b1 = bias[col + 1]; }
            float v00 = acc[mt][nt][0] + b0, v01 = acc[mt][nt][1] + b1;
            float v10 = acc[mt][nt][2] + b0, v11 = acc[mt][nt][3] + b1;
            if (RELU) {
                v00 = fmaxf(v00, 0.f); v01 = fmaxf(v01, 0.f);
                v10 = fmaxf(v10, 0.f); v11 = fmaxf(v11, 0.f);
            }
            if constexpr (sizeof(TO) == 4) {
                *(float2*)((float*)C + (size_t)row * ldc + col) = make_float2(v00, v01);
                *(float2*)((float*)C + (size_t)(row + 8) * ldc + col) = make_float2(v10, v11);
            } else {
                __nv_bfloat162 p0, p1;
                p0.x = __float2bfloat16_rn(v00); p0.y = __float2bfloat16_rn(v01);
                p1.x = __float2bfloat16_rn(v10); p1.y = __float2bfloat16_rn(v11);
                *(__nv_bfloat162*)((bf16*)C + (size_t)row * ldc + col) = p0;
                *(__nv_bfloat162*)((bf16*)C + (size_t)(row + 8) * ldc + col) = p1;
            }
        }
    }
    #undef FILL
}

#define SMEM_NT (STAGES * (ABYTES + ABYTES))      // 81920
#define SMEM_NN (STAGES * (ABYTES + 32 * PBN))    // 75776

// ---------------------------------------------------------------------------
__global__ void cvt_bf(const float* __restrict__ in, bf16* __restrict__ out, int n4)
{
    int i = blockIdx.x * 256 + threadIdx.x;
    if (i < n4) {
        float4 v = ((const float4*)in)[i];
        __nv_bfloat162 a, b;
        a.x = __float2bfloat16_rn(v.x); a.y = __float2bfloat16_rn(v.y);
        b.x = __float2bfloat16_rn(v.z); b.y = __float2bfloat16_rn(v.w);
        ((__nv_bfloat162*)out)[2 * i]     = a;
        ((__nv_bfloat162*)out)[2 * i + 1] = b;
    }
}

// ---------------------------------------------------------------------------
// Fused weight transposes: one launch, flat 32x32-tile grid with job decode.
// ---------------------------------------------------------------------------
__global__ void trp_all(const float* __restrict__ W1s, const float* __restrict__ W2s,
                        const float* __restrict__ W3s,
                        bf16* __restrict__ w1d, bf16* __restrict__ w2d,
                        bf16* __restrict__ w3d)
{
    __shared__ float t[32][33];
    int b = blockIdx.x;
    const float* in; bf16* out; int R, Cc, tc, tile;
    if (b < 512)       { in = W1s; out = w1d; R = DIN;  Cc = 2*DIN; tc = 32; tile = b; }
    else if (b < 1536) { in = W2s; out = w2d; R = 2*DIN; Cc = DH;   tc = 32; tile = b - 512; }
    else               { in = W3s; out = w3d; R = DH;   Cc = DH2;  tc = 16; tile = b - 1536; }
    const int r0 = (tile / tc) * 32, c0 = (tile % tc) * 32;
    const int x = threadIdx.x, y = threadIdx.y;   // 32 x 8
    #pragma unroll
    for (int i = 0; i < 32; i += 8)
        t[y + i][x] = in[(size_t)(r0 + y + i) * Cc + c0 + x];
    __syncthreads();
    #pragma unroll
    for (int i = 0; i < 32; i += 8)
        out[(size_t)(c0 + y + i) * R + r0 + x] = __float2bfloat16_rn(t[x][y + i]);
}

// ---------------------------------------------------------------------------
// Vectorized single-pass causal softmax: fp32 scores -> bf16 weights.
// ---------------------------------------------------------------------------
__global__ void softmax_causal(const float* __restrict__ Sc, bf16* __restrict__ W)
{
    const int row = blockIdx.x, bb = blockIdx.y;
    const float4* r4 = (const float4*)(Sc + (size_t)bb * S_ * S_ + (size_t)row * S_);
    bf16* w = W + (size_t)bb * S_ * S_ + (size_t)row * S_;
    const int n = row + 1;
    const int bend = ((row >> 7) + 1) << 7;
    const int tid = threadIdx.x;
    const int lane = tid & 31, warp = tid >> 5;
    const int j0 = tid * 8;
    __shared__ float red[8];

    float v[8];
    if (j0 < n) {
        float4 a = r4[tid * 2];
        float4 b = r4[tid * 2 + 1];
        v[0] = a.x; v[1] = a.y; v[2] = a.z; v[3] = a.w;
        v[4] = b.x; v[5] = b.y; v[6] = b.z; v[7] = b.w;
        #pragma unroll
        for (int e = 0; e < 8; e++)
            if (j0 + e >= n) v[e] = -INFINITY;
    } else {
        #pragma unroll
        for (int e = 0; e < 8; e++) v[e] = -INFINITY;
    }

    float m = v[0];
    #pragma unroll
    for (int e = 1; e < 8; e++) m = fmaxf(m, v[e]);
    #pragma unroll
    for (int s = 16; s > 0; s >>= 1) m = fmaxf(m, __shfl_xor_sync(~0u, m, s));
    if (lane == 0) red[warp] = m;
    __syncthreads();
    m = red[lane & 7];
    #pragma unroll
    for (int s = 4; s > 0; s >>= 1) m = fmaxf(m, __shfl_xor_sync(~0u, m, s));

    float sum = 0.0f;
    #pragma unroll
    for (int e = 0; e < 8; e++) {
        v[e] = (v[e] == -INFINITY) ? 0.0f : __expf(v[e] - m);
        sum += v[e];
    }
    #pragma unroll
    for (int s = 16; s > 0; s >>= 1) sum += __shfl_xor_sync(~0u, sum, s);
    __syncthreads();
    if (lane == 0) red[warp] = sum;
    __syncthreads();
    sum = red[lane & 7];
    #pragma unroll
    for (int s = 4; s > 0; s >>= 1) sum += __shfl_xor_sync(~0u, sum, s);
    const float inv = 1.0f / sum;

    if (j0 < bend) {
        __nv_bfloat162 p[4];
        #pragma unroll
        for (int k = 0; k < 4; k++) {
            p[k].x = __float2bfloat16_rn(v[2 * k] * inv);
            p[k].y = __float2bfloat16_rn(v[2 * k + 1] * inv);
        }
        *(uint4*)(w + j0) = *(uint4*)p;
    }
}

// ---------------------------------------------------------------------------
// Head: out = log_softmax(o @ W4 + b4). One warp per row; float4 loads.
// ---------------------------------------------------------------------------
__global__ void head_kernel(const float* __restrict__ O, const float* __restrict__ W4,
                            const float* __restrict__ b4, float* __restrict__ out)
{
    __shared__ float w[DH2 * DOUT];
    const int tid = threadIdx.x;
    for (int i = tid; i < DH2 * DOUT; i += 256) w[i] = W4[i];
    __syncthreads();

    const int warp = tid >> 5, lane = tid & 31;
    const int row = blockIdx.x * 8 + warp;
    const float4* o4 = (const float4*)(O + (size_t)row * DH2);

    float acc[DOUT];
    #pragma unroll
    for (int j = 0; j < DOUT; j++) acc[j] = 0.0f;
    #pragma unroll
    for (int it = 0; it < 4; it++) {
        float4 ov = o4[lane + it * 32];
        const int kb = (lane + it * 32) * 4;
        float oe[4] = {ov.x, ov.y, ov.z, ov.w};
        #pragma unroll
        for (int e = 0; e < 4; e++) {
            const float* wk = &w[(kb + e) * DOUT];
            #pragma unroll
            for (int j = 0; j < DOUT; j++) acc[j] = fmaf(oe[e], wk[j], acc[j]);
        }
    }
    #pragma unroll
    for (int j = 0; j < DOUT; j++)
        #pragma unroll
        for (int s = 16; s > 0; s >>= 1)
            acc[j] += __shfl_xor_sync(0xffffffffu, acc[j], s);

    if (lane == 0) {
        float m = -INFINITY;
        #pragma unroll
        for (int j = 0; j < DOUT; j++) { acc[j] += b4[j]; m = fmaxf(m, acc[j]); }
        float sum = 0.0f;
        #pragma unroll
        for (int j = 0; j < DOUT; j++) sum += expf(acc[j] - m);
        float lse = m + logf(sum);
        #pragma unroll
        for (int j = 0; j < DOUT; j++)
            out[(size_t)row * DOUT + j] = acc[j] - lse;
    }
}

// ---------------------------------------------------------------------------
extern "C" void kernel_launch(void* const* d_in, const int* in_sizes, int n_in,
                              void* d_out, int out_size)
{
    const float* input = (const float*)d_in[0];
    const float* gamev = (const float*)d_in[1];
    const float* userv = (const float*)d_in[2];
    const float* W1 = (const float*)d_in[3];
    const float* b1 = (const float*)d_in[4];
    const float* W2 = (const float*)d_in[5];
    const float* b2 = (const float*)d_in[6];
    const float* W3 = (const float*)d_in[7];
    const float* b3 = (const float*)d_in[8];
    const float* W4 = (const float*)d_in[9];
    const float* b4 = (const float*)d_in[10];
    float* out = (float*)d_out;

    bf16 *inb, *w1t, *w2t, *w3t, *h1b, *hb, *attnb, *ctxb;
    float *attn, *o;
    cudaGetSymbolAddress((void**)&inb,   g_inb);
    cudaGetSymbolAddress((void**)&w1t,   g_w1t);
    cudaGetSymbolAddress((void**)&w2t,   g_w2t);
    cudaGetSymbolAddress((void**)&w3t,   g_w3t);
    cudaGetSymbolAddress((void**)&h1b,   g_h1b);
    cudaGetSymbolAddress((void**)&hb,    g_hb);
    cudaGetSymbolAddress((void**)&attn,  g_attn);
    cudaGetSymbolAddress((void**)&attnb, g_attnb);
    cudaGetSymbolAddress((void**)&ctxb,  g_ctxb);
    cudaGetSymbolAddress((void**)&o,     g_o);

    //                  TO     RELU  BIAS  BNN    TRI    KCUT  REVY
    auto g_mlpB = gemm_bf<bf16,  true,  true,  false, false, false, false>;
    auto g_sc   = gemm_bf<float, false, false, false, true,  false, false>;
    auto g_ctxk = gemm_bf<bf16,  false, false, true,  false, true,  true >;
    auto g_mlpF = gemm_bf<float, true,  true,  false, false, false, false>;
    cudaFuncSetAttribute(g_mlpB, cudaFuncAttributeMaxDynamicSharedMemorySize, SMEM_NT);
    cudaFuncSetAttribute(g_sc,   cudaFuncAttributeMaxDynamicSharedMemorySize, SMEM_NT);
    cudaFuncSetAttribute(g_ctxk, cudaFuncAttributeMaxDynamicSharedMemorySize, SMEM_NN);
    cudaFuncSetAttribute(g_mlpF, cudaFuncAttributeMaxDynamicSharedMemorySize, SMEM_NT);

    // pass-through first (independent; off the critical tail)
    size_t off = (size_t)M_ * DOUT;
    cudaMemcpyAsync(out + off, gamev, (size_t)in_sizes[1] * sizeof(float),
                    cudaMemcpyDeviceToDevice);
    cudaMemcpyAsync(out + off + in_sizes[1], userv, (size_t)in_sizes[2] * sizeof(float),
                    cudaMemcpyDeviceToDevice);

    // operand conversions (2 launches)
    cvt_bf<<<(M_ * DIN / 4 + 255) / 256, 256>>>(input, inb, M_ * DIN / 4);
    trp_all<<<2048, dim3(32, 8)>>>(W1, W2, W3, w1t, w2t, w3t);

    // 1) h1 = relu(in @ W1 + b1)    M=32768 N=1024 K=512
    g_mlpB<<<dim3(8, 256, 1), 256, SMEM_NT>>>(inb, w1t, b1, h1b,
        DIN, DIN, 2*DIN, DIN, 0, 0, 0);
    // 2) h = relu(h1 @ W2 + b2)     M=32768 N=1024 K=1024
    g_mlpB<<<dim3(8, 256, 1), 256, SMEM_NT>>>(h1b, w2t, b2, hb,
        2*DIN, 2*DIN, DH, 2*DIN, 0, 0, 0);
    // 3) scores = H @ H^T per batch: triangular grid + diagonal sub-tile skip
    g_sc<<<dim3(136, 1, B_), 256, SMEM_NT>>>(hb, hb, nullptr, attn,
        DH, DH, S_, DH, (size_t)S_*DH, (size_t)S_*DH, (size_t)S_*S_);
    // 4) causal softmax fp32 -> bf16 weights (vectorized, bounded writes)
    softmax_causal<<<dim3(S_, B_), 256>>>(attn, attnb);
    // 5) ctx = attn @ H per batch (NN, K cutoff, LPT order)
    g_ctxk<<<dim3(8, 16, B_), 256, SMEM_NN>>>(attnb, hb, nullptr, ctxb,
        S_, DH, DH, S_, (size_t)S_*S_, (size_t)S_*DH, (size_t)S_*DH);
    // 6) o = relu(ctx @ W3 + b3)    M=32768 N=512 K=1024 -> fp32
    g_mlpF<<<dim3(4, 256, 1), 256, SMEM_NT>>>(ctxb, w3t, b3, o,
        DH, DH, DH2, DH, 0, 0, 0);
    // 7) head + log_softmax
    head_kernel<<<M_ / 8, 256>>>(o, W4, b4, out);
}

// round 14
// speedup vs baseline: 1.0355x; 1.0355x over previous
#include <cuda_runtime.h>
#include <cuda_bf16.h>
#include <cstdint>
#include <math.h>

// ---------------- problem constants ----------------
#define B_   16
#define S_   2048
#define DIN  512
#define DH   1024
#define DH2  512
#define DOUT 10
#define M_   (B_ * S_)   // 32768

typedef __nv_bfloat16 bf16;

// ---------------- scratch (device globals; allocation-free) ----------------
__device__ bf16  g_inb [(size_t)M_ * DIN];
__device__ bf16  g_w1t [(size_t)(2 * DIN) * DIN];   // [N,K] bf16
__device__ bf16  g_w2t [(size_t)DH * (2 * DIN)];
__device__ bf16  g_w3t [(size_t)DH2 * DH];
__device__ bf16  g_h1b [(size_t)M_ * (2 * DIN)];
__device__ bf16  g_hb  [(size_t)M_ * DH];
__device__ float g_attn[(size_t)B_ * S_ * S_];      // fp32 scores
__device__ bf16  g_attnb[(size_t)B_ * S_ * S_];     // bf16 attn weights
__device__ bf16  g_ctxb[(size_t)M_ * DH];
__device__ float g_o   [(size_t)M_ * DH2];

// ---------------- helpers ----------------
__device__ __forceinline__ uint32_t smem_u32(const void* p) {
    uint32_t a;
    asm("{ .reg .u64 t; cvta.to.shared.u64 t, %1; cvt.u32.u64 %0, t; }" : "=r"(a) : "l"(p));
    return a;
}
__device__ __forceinline__ void cp16(uint32_t dst, const void* src) {
    asm volatile("cp.async.cg.shared.global [%0], [%1], 16;" :: "r"(dst), "l"(src));
}
#define CP_COMMIT() asm volatile("cp.async.commit_group;" ::: "memory")
#define CP_WAIT(N)  asm volatile("cp.async.wait_group %0;" :: "n"(N) : "memory")

__device__ __forceinline__ void ldsm_x4(uint32_t* r, uint32_t addr) {
    asm volatile("ldmatrix.sync.aligned.m8n8.x4.shared.b16 {%0,%1,%2,%3}, [%4];"
        : "=r"(r[0]), "=r"(r[1]), "=r"(r[2]), "=r"(r[3]) : "r"(addr));
}
__device__ __forceinline__ void ldsm_x4_t(uint32_t* r, uint32_t addr) {
    asm volatile("ldmatrix.sync.aligned.m8n8.x4.trans.shared.b16 {%0,%1,%2,%3}, [%4];"
        : "=r"(r[0]), "=r"(r[1]), "=r"(r[2]), "=r"(r[3]) : "r"(addr));
}
__device__ __forceinline__ void mma_bf16(float* d, const uint32_t* a, const uint32_t* b) {
    asm volatile(
        "mma.sync.aligned.m16n8k16.row.col.f32.bf16.bf16.f32 "
        "{%0,%1,%2,%3}, {%4,%5,%6,%7}, {%8,%9}, {%0,%1,%2,%3};"
        : "+f"(d[0]), "+f"(d[1]), "+f"(d[2]), "+f"(d[3])
        : "r"(a[0]), "r"(a[1]), "r"(a[2]), "r"(a[3]), "r"(b[0]), "r"(b[1]));
}

// ---------------- GEMM geometry ----------------
// CTA 128x128, BK=32 bf16, 4-stage cp.async ring (1 sync/stage),
// 8 warps = 2(m) x 4(n), warp tile 64x32, m16n8k16.
#define PA 80
#define PBN 272
#define ABYTES (128 * PA)          // 10240
#define STAGES 4

// TRI: 1D triangular tile grid (scores): blockIdx.x -> (bi>=bj), z = batch.
template<typename TO, bool RELU, bool HAS_BIAS, bool BNN, bool TRI, bool KCUT, bool REVY>
__global__ void __launch_bounds__(256, 2)
gemm_bf(const bf16* __restrict__ A, const bf16* __restrict__ Bsrc,
        const float* __restrict__ bias, TO* __restrict__ C,
        int lda, int ldb, int ldc, int K,
        size_t strA, size_t strB, size_t strC)
{
    constexpr int BBYTES = BNN ? (32 * PBN) : ABYTES;
    constexpr int SB     = ABYTES + BBYTES;

    int m0, n0;
    if (TRI) {
        // decode x -> (bi, bj), bi >= bj, bi in [0,16)
        const int x = blockIdx.x;
        int bi = (int)((sqrtf(8.0f * (float)x + 1.0f) - 1.0f) * 0.5f);
        while ((bi + 1) * (bi + 2) / 2 <= x) bi++;
        while (bi * (bi + 1) / 2 > x) bi--;
        const int bj = x - bi * (bi + 1) / 2;
        m0 = bi * 128;
        n0 = bj * 128;
    } else {
        const int by = REVY ? (gridDim.y - 1 - blockIdx.y) : blockIdx.y;
        m0 = by * 128;
        n0 = blockIdx.x * 128;
    }

    A    += (size_t)blockIdx.z * strA;
    Bsrc += (size_t)blockIdx.z * strB;
    C    += (size_t)blockIdx.z * strC;

    const int Keff = KCUT ? ((m0 + 128) < K ? (m0 + 128) : K) : K;
    const int NC = Keff >> 5;

    extern __shared__ char smem[];
    const uint32_t sb = smem_u32(smem);

    const int tid  = threadIdx.x;
    const int lane = tid & 31;
    const int wid  = tid >> 5;
    const int wm   = wid & 1;
    const int wn   = wid >> 1;
    const int fc   = lane & 3;
    const int fr   = lane >> 2;

    const int f_row = tid >> 1, f_hf = tid & 1;
    const int bn_r  = tid >> 4, bn_c = tid & 15;

    #define FILL(stage, c) do {                                                    \
        const uint32_t _ab = sb + (stage) * SB;                                     \
        const uint32_t _bb = _ab + ABYTES;                                          \
        const int _k = (c) << 5;                                                    \
        _Pragma("unroll")                                                           \
        for (int j = 0; j < 2; j++) {                                               \
            const int ch = f_hf * 2 + j;                                            \
            cp16(_ab + (uint32_t)(f_row * PA + ch * 16),                            \
                 A + (size_t)(m0 + f_row) * lda + _k + ch * 8);                     \
        }                                                                           \
        if (BNN) {                                                                  \
            cp16(_bb + (uint32_t)(bn_r * PBN + bn_c * 16),                          \
                 Bsrc + (size_t)(_k + bn_r) * ldb + n0 + bn_c * 8);                 \
            cp16(_bb + (uint32_t)((bn_r + 16) * PBN + bn_c * 16),                   \
                 Bsrc + (size_t)(_k + bn_r + 16) * ldb + n0 + bn_c * 8);            \
        } else {                                                                    \
            _Pragma("unroll")                                                       \
            for (int j = 0; j < 2; j++) {                                           \
                const int ch = f_hf * 2 + j;                                        \
                cp16(_bb + (uint32_t)(f_row * PA + ch * 16),                        \
                     Bsrc + (size_t)(n0 + f_row) * ldb + _k + ch * 8);              \
            }                                                                       \
        }                                                                           \
    } while (0)

    float acc[4][4][4];
    #pragma unroll
    for (int i = 0; i < 4; i++)
        #pragma unroll
        for (int j = 0; j < 4; j++)
            #pragma unroll
            for (int r = 0; r < 4; r++) acc[i][j][r] = 0.0f;

    #pragma unroll
    for (int s = 0; s < STAGES - 1; s++) {
        if (s < NC) FILL(s, s);
        CP_COMMIT();
    }

    const uint32_t aoff   = (uint32_t)((lane & 15) * PA + (lane >> 4) * 16);
    const uint32_t boffNT = (uint32_t)((((lane >> 4) & 1) * 8 + (lane & 7)) * PA
                                       + ((lane >> 3) & 1) * 16);
    const uint32_t boffNN = (uint32_t)((lane & 15) * PBN + (lane >> 4) * 16);

    for (int c = 0; c < NC; ++c) {
        CP_WAIT(STAGES - 2);
        __syncthreads();
        if (c + STAGES - 1 < NC) FILL((c + STAGES - 1) & 3, c + STAGES - 1);
        CP_COMMIT();

        const uint32_t stb   = sb + (c & 3) * SB;
        const uint32_t aBase = stb + (uint32_t)(wm * 64) * PA + aoff;
        const uint32_t bBase = BNN
            ? (stb + ABYTES + (uint32_t)(wn * 32) * 2 + boffNN)
            : (stb + ABYTES + (uint32_t)(wn * 32) * PA + boffNT);

        #pragma unroll
        for (int s = 0; s < 2; ++s) {
            uint32_t bf[4][2];
            if (BNN) {
                uint32_t t[4];
                ldsm_x4_t(t, bBase + (uint32_t)(s * 16) * PBN);
                bf[0][0] = t[0]; bf[0][1] = t[1]; bf[1][0] = t[2]; bf[1][1] = t[3];
                ldsm_x4_t(t, bBase + (uint32_t)(s * 16) * PBN + 32);
                bf[2][0] = t[0]; bf[2][1] = t[1]; bf[3][0] = t[2]; bf[3][1] = t[3];
            } else {
                uint32_t t[4];
                ldsm_x4(t, bBase + s * 32);
                bf[0][0] = t[0]; bf[0][1] = t[1]; bf[1][0] = t[2]; bf[1][1] = t[3];
                ldsm_x4(t, bBase + 16 * PA + s * 32);
                bf[2][0] = t[0]; bf[2][1] = t[1]; bf[3][0] = t[2]; bf[3][1] = t[3];
            }
            #pragma unroll
            for (int mt = 0; mt < 4; ++mt) {
                uint32_t af[4];
                ldsm_x4(af, aBase + (uint32_t)(mt * 16) * PA + s * 32);
                #pragma unroll
                for (int nt = 0; nt < 4; ++nt)
                    mma_bf16(acc[mt][nt], af, bf[nt]);
            }
        }
    }

    #pragma unroll
    for (int mt = 0; mt < 4; ++mt) {
        #pragma unroll
        for (int nt = 0; nt < 4; ++nt) {
            const int row = m0 + wm * 64 + mt * 16 + fr;
            const int col = n0 + wn * 32 + nt * 8 + 2 * fc;
            float b0 = 0.f, b1 = 0.f;
            if (HAS_BIAS) { b0 = bias[col]; b1 = bias[col + 1]; }
            float v00 = acc[mt][nt][0] + b0, v01 = acc[mt][nt][1] + b1;
            float v10 = acc[mt][nt][2] + b0, v11 = acc[mt][nt][3] + b1;
            if (RELU) {
                v00 = fmaxf(v00, 0.f); v01 = fmaxf(v01, 0.f);
                v10 = fmaxf(v10, 0.f); v11 = fmaxf(v11, 0.f);
            }
            if constexpr (sizeof(TO) == 4) {
                *(float2*)((float*)C + (size_t)row * ldc + col) = make_float2(v00, v01);
                *(float2*)((float*)C + (size_t)(row + 8) * ldc + col) = make_float2(v10, v11);
            } else {
                __nv_bfloat162 p0, p1;
                p0.x = __float2bfloat16_rn(v00); p0.y = __float2bfloat16_rn(v01);
                p1.x = __float2bfloat16_rn(v10); p1.y = __float2bfloat16_rn(v11);
                *(__nv_bfloat162*)((bf16*)C + (size_t)row * ldc + col) = p0;
                *(__nv_bfloat162*)((bf16*)C + (size_t)(row + 8) * ldc + col) = p1;
            }
        }
    }
    #undef FILL
}

#define SMEM_NT (STAGES * (ABYTES + ABYTES))      // 81920
#define SMEM_NN (STAGES * (ABYTES + 32 * PBN))    // 75776

// ---------------------------------------------------------------------------
__global__ void cvt_bf(const float* __restrict__ in, bf16* __restrict__ out, int n4)
{
    int i = blockIdx.x * 256 + threadIdx.x;
    if (i < n4) {
        float4 v = ((const float4*)in)[i];
        __nv_bfloat162 a, b;
        a.x = __float2bfloat16_rn(v.x); a.y = __float2bfloat16_rn(v.y);
        b.x = __float2bfloat16_rn(v.z); b.y = __float2bfloat16_rn(v.w);
        ((__nv_bfloat162*)out)[2 * i]     = a;
        ((__nv_bfloat162*)out)[2 * i + 1] = b;
    }
}

// ---------------------------------------------------------------------------
// Fused weight transposes: one launch, flat 32x32-tile grid with job decode.
// ---------------------------------------------------------------------------
__global__ void trp_all(const float* __restrict__ W1s, const float* __restrict__ W2s,
                        const float* __restrict__ W3s,
                        bf16* __restrict__ w1d, bf16* __restrict__ w2d,
                        bf16* __restrict__ w3d)
{
    __shared__ float t[32][33];
    int b = blockIdx.x;
    const float* in; bf16* out; int R, Cc, tc, tile;
    if (b < 512)       { in = W1s; out = w1d; R = DIN;  Cc = 2*DIN; tc = 32; tile = b; }
    else if (b < 1536) { in = W2s; out = w2d; R = 2*DIN; Cc = DH;   tc = 32; tile = b - 512; }
    else               { in = W3s; out = w3d; R = DH;   Cc = DH2;  tc = 16; tile = b - 1536; }
    const int r0 = (tile / tc) * 32, c0 = (tile % tc) * 32;
    const int x = threadIdx.x, y = threadIdx.y;   // 32 x 8
    #pragma unroll
    for (int i = 0; i < 32; i += 8)
        t[y + i][x] = in[(size_t)(r0 + y + i) * Cc + c0 + x];
    __syncthreads();
    #pragma unroll
    for (int i = 0; i < 32; i += 8)
        out[(size_t)(c0 + y + i) * R + r0 + x] = __float2bfloat16_rn(t[x][y + i]);
}

// ---------------------------------------------------------------------------
// Vectorized single-pass causal softmax: fp32 scores -> bf16 weights.
// ---------------------------------------------------------------------------
__global__ void softmax_causal(const float* __restrict__ Sc, bf16* __restrict__ W)
{
    const int row = blockIdx.x, bb = blockIdx.y;
    const float4* r4 = (const float4*)(Sc + (size_t)bb * S_ * S_ + (size_t)row * S_);
    bf16* w = W + (size_t)bb * S_ * S_ + (size_t)row * S_;
    const int n = row + 1;
    const int bend = ((row >> 7) + 1) << 7;
    const int tid = threadIdx.x;
    const int lane = tid & 31, warp = tid >> 5;
    const int j0 = tid * 8;
    __shared__ float red[8];

    float v[8];
    if (j0 < n) {
        float4 a = r4[tid * 2];
        float4 b = r4[tid * 2 + 1];
        v[0] = a.x; v[1] = a.y; v[2] = a.z; v[3] = a.w;
        v[4] = b.x; v[5] = b.y; v[6] = b.z; v[7] = b.w;
        #pragma unroll
        for (int e = 0; e < 8; e++)
            if (j0 + e >= n) v[e] = -INFINITY;
    } else {
        #pragma unroll
        for (int e = 0; e < 8; e++) v[e] = -INFINITY;
    }

    float m = v[0];
    #pragma unroll
    for (int e = 1; e < 8; e++) m = fmaxf(m, v[e]);
    #pragma unroll
    for (int s = 16; s > 0; s >>= 1) m = fmaxf(m, __shfl_xor_sync(~0u, m, s));
    if (lane == 0) red[warp] = m;
    __syncthreads();
    m = red[lane & 7];
    #pragma unroll
    for (int s = 4; s > 0; s >>= 1) m = fmaxf(m, __shfl_xor_sync(~0u, m, s));

    float sum = 0.0f;
    #pragma unroll
    for (int e = 0; e < 8; e++) {
        v[e] = (v[e] == -INFINITY) ? 0.0f : __expf(v[e] - m);
        sum += v[e];
    }
    #pragma unroll
    for (int s = 16; s > 0; s >>= 1) sum += __shfl_xor_sync(~0u, sum, s);
    __syncthreads();
    if (lane == 0) red[warp] = sum;
    __syncthreads();
    sum = red[lane & 7];
    #pragma unroll
    for (int s = 4; s > 0; s >>= 1) sum += __shfl_xor_sync(~0u, sum, s);
    const float inv = 1.0f / sum;

    if (j0 < bend) {
        __nv_bfloat162 p[4];
        #pragma unroll
        for (int k = 0; k < 4; k++) {
            p[k].x = __float2bfloat16_rn(v[2 * k] * inv);
            p[k].y = __float2bfloat16_rn(v[2 * k + 1] * inv);
        }
        *(uint4*)(w + j0) = *(uint4*)p;
    }
}

// ---------------------------------------------------------------------------
// Head: out = log_softmax(o @ W4 + b4). One warp per row; float4 loads.
// ---------------------------------------------------------------------------
__global__ void head_kernel(const float* __restrict__ O, const float* __restrict__ W4,
                            const float* __restrict__ b4, float* __restrict__ out)
{
    __shared__ float w[DH2 * DOUT];
    const int tid = threadIdx.x;
    for (int i = tid; i < DH2 * DOUT; i += 256) w[i] = W4[i];
    __syncthreads();

    const int warp = tid >> 5, lane = tid & 31;
    const int row = blockIdx.x * 8 + warp;
    const float4* o4 = (const float4*)(O + (size_t)row * DH2);

    float acc[DOUT];
    #pragma unroll
    for (int j = 0; j < DOUT; j++) acc[j] = 0.0f;
    #pragma unroll
    for (int it = 0; it < 4; it++) {
        float4 ov = o4[lane + it * 32];
        const int kb = (lane + it * 32) * 4;
        float oe[4] = {ov.x, ov.y, ov.z, ov.w};
        #pragma unroll
        for (int e = 0; e < 4; e++) {
            const float* wk = &w[(kb + e) * DOUT];
            #pragma unroll
            for (int j = 0; j < DOUT; j++) acc[j] = fmaf(oe[e], wk[j], acc[j]);
        }
    }
    #pragma unroll
    for (int j = 0; j < DOUT; j++)
        #pragma unroll
        for (int s = 16; s > 0; s >>= 1)
            acc[j] += __shfl_xor_sync(0xffffffffu, acc[j], s);

    if (lane == 0) {
        float m = -INFINITY;
        #pragma unroll
        for (int j = 0; j < DOUT; j++) { acc[j] += b4[j]; m = fmaxf(m, acc[j]); }
        float sum = 0.0f;
        #pragma unroll
        for (int j = 0; j < DOUT; j++) sum += expf(acc[j] - m);
        float lse = m + logf(sum);
        #pragma unroll
        for (int j = 0; j < DOUT; j++)
            out[(size_t)row * DOUT + j] = acc[j] - lse;
    }
}

// ---------------------------------------------------------------------------
extern "C" void kernel_launch(void* const* d_in, const int* in_sizes, int n_in,
                              void* d_out, int out_size)
{
    const float* input = (const float*)d_in[0];
    const float* gamev = (const float*)d_in[1];
    const float* userv = (const float*)d_in[2];
    const float* W1 = (const float*)d_in[3];
    const float* b1 = (const float*)d_in[4];
    const float* W2 = (const float*)d_in[5];
    const float* b2 = (const float*)d_in[6];
    const float* W3 = (const float*)d_in[7];
    const float* b3 = (const float*)d_in[8];
    const float* W4 = (const float*)d_in[9];
    const float* b4 = (const float*)d_in[10];
    float* out = (float*)d_out;

    bf16 *inb, *w1t, *w2t, *w3t, *h1b, *hb, *attnb, *ctxb;
    float *attn, *o;
    cudaGetSymbolAddress((void**)&inb,   g_inb);
    cudaGetSymbolAddress((void**)&w1t,   g_w1t);
    cudaGetSymbolAddress((void**)&w2t,   g_w2t);
    cudaGetSymbolAddress((void**)&w3t,   g_w3t);
    cudaGetSymbolAddress((void**)&h1b,   g_h1b);
    cudaGetSymbolAddress((void**)&hb,    g_hb);
    cudaGetSymbolAddress((void**)&attn,  g_attn);
    cudaGetSymbolAddress((void**)&attnb, g_attnb);
    cudaGetSymbolAddress((void**)&ctxb,  g_ctxb);
    cudaGetSymbolAddress((void**)&o,     g_o);

    //                  TO     RELU  BIAS  BNN    TRI    KCUT  REVY
    auto g_mlpB = gemm_bf<bf16,  true,  true,  false, false, false, false>;
    auto g_sc   = gemm_bf<float, false, false, false, true,  false, false>;
    auto g_ctxk = gemm_bf<bf16,  false, false, true,  false, true,  true >;
    auto g_mlpF = gemm_bf<float, true,  true,  false, false, false, false>;
    cudaFuncSetAttribute(g_mlpB, cudaFuncAttributeMaxDynamicSharedMemorySize, SMEM_NT);
    cudaFuncSetAttribute(g_sc,   cudaFuncAttributeMaxDynamicSharedMemorySize, SMEM_NT);
    cudaFuncSetAttribute(g_ctxk, cudaFuncAttributeMaxDynamicSharedMemorySize, SMEM_NN);
    cudaFuncSetAttribute(g_mlpF, cudaFuncAttributeMaxDynamicSharedMemorySize, SMEM_NT);

    // pass-through first (independent; off the critical tail)
    size_t off = (size_t)M_ * DOUT;
    cudaMemcpyAsync(out + off, gamev, (size_t)in_sizes[1] * sizeof(float),
                    cudaMemcpyDeviceToDevice);
    cudaMemcpyAsync(out + off + in_sizes[1], userv, (size_t)in_sizes[2] * sizeof(float),
                    cudaMemcpyDeviceToDevice);

    // operand conversions (2 launches)
    cvt_bf<<<(M_ * DIN / 4 + 255) / 256, 256>>>(input, inb, M_ * DIN / 4);
    trp_all<<<2048, dim3(32, 8)>>>(W1, W2, W3, w1t, w2t, w3t);

    // 1) h1 = relu(in @ W1 + b1)    M=32768 N=1024 K=512
    g_mlpB<<<dim3(8, 256, 1), 256, SMEM_NT>>>(inb, w1t, b1, h1b,
        DIN, DIN, 2*DIN, DIN, 0, 0, 0);
    // 2) h = relu(h1 @ W2 + b2)     M=32768 N=1024 K=1024
    g_mlpB<<<dim3(8, 256, 1), 256, SMEM_NT>>>(h1b, w2t, b2, hb,
        2*DIN, 2*DIN, DH, 2*DIN, 0, 0, 0);
    // 3) scores = H @ H^T per batch: compact triangular grid, 136 tiles/batch
    g_sc<<<dim3(136, 1, B_), 256, SMEM_NT>>>(hb, hb, nullptr, attn,
        DH, DH, S_, DH, (size_t)S_*DH, (size_t)S_*DH, (size_t)S_*S_);
    // 4) causal softmax fp32 -> bf16 weights (vectorized, bounded writes)
    softmax_causal<<<dim3(S_, B_), 256>>>(attn, attnb);
    // 5) ctx = attn @ H per batch (NN, K cutoff, LPT order)
    g_ctxk<<<dim3(8, 16, B_), 256, SMEM_NN>>>(attnb, hb, nullptr, ctxb,
        S_, DH, DH, S_, (size_t)S_*S_, (size_t)S_*DH, (size_t)S_*DH);
    // 6) o = relu(ctx @ W3 + b3)    M=32768 N=512 K=1024 -> fp32
    g_mlpF<<<dim3(4, 256, 1), 256, SMEM_NT>>>(ctxb, w3t, b3, o,
        DH, DH, DH2, DH, 0, 0, 0);
    // 7) head + log_softmax
    head_kernel<<<M_ / 8, 256>>>(o, W4, b4, out);
}